// round 6
// baseline (speedup 1.0000x reference)
#include <cuda_runtime.h>

// ---------------- problem constants ----------------
#define NMAX 50000
#define EMAX 800000
#define D    128
#define DLAT 64
#define BN_EPS 1e-5f
#define SCAN_B 256
#define NBLK ((NMAX + SCAN_B - 1) / SCAN_B)

// ---------------- packed f32x2 helpers (Blackwell double-rate fp32) --------
__device__ __forceinline__ unsigned long long pack2(float lo, float hi) {
    unsigned long long r;
    asm("mov.b64 %0, {%1, %2};" : "=l"(r) : "f"(lo), "f"(hi));
    return r;
}
__device__ __forceinline__ unsigned long long fma2(unsigned long long a,
                                                   unsigned long long b,
                                                   unsigned long long c) {
    unsigned long long d;
    asm("fma.rn.f32x2 %0, %1, %2, %3;" : "=l"(d) : "l"(a), "l"(b), "l"(c));
    return d;
}
__device__ __forceinline__ void unpack2(unsigned long long v, float& lo, float& hi) {
    asm("mov.b64 {%0, %1}, %2;" : "=f"(lo), "=f"(hi) : "l"(v));
}

// ---------------- scratch (device globals; no allocation) ----------------
__device__ int   g_cnt[NMAX];
__device__ int   g_rowptr[NMAX + 1];
__device__ int   g_cursor[NMAX];
__device__ int   g_srcs[EMAX];
__device__ float g_w[EMAX];
__device__ int   g_bsum[NBLK];
__device__ int   g_boff[NBLK];
__device__ float g_isd[NMAX];
__device__ float g_invdeg[NMAX];
__device__ float g_h0[(size_t)NMAX * D];
__device__ float g_h [(size_t)NMAX * D];
__device__ float g_aggh[(size_t)NMAX * D];
__device__ float g_sum[D];
__device__ float g_sumsq[D];
__device__ float g_scale[D];
__device__ float g_shift[D];
__device__ float g_Wcat[D * D];
__device__ float g_bcat[D];

// ---------------- init: zero counters/accums, build Wcat/bcat ----------------
__global__ void k_init(const float* __restrict__ Wmu, const float* __restrict__ Wls,
                       const float* __restrict__ bmu, const float* __restrict__ bls,
                       int N) {
    int i = blockIdx.x * blockDim.x + threadIdx.x;
    if (i < N) g_cnt[i] = 0;
    if (i < D) {
        g_sum[i] = 0.0f;
        g_sumsq[i] = 0.0f;
        g_bcat[i] = (i < DLAT) ? bmu[i] : bls[i - DLAT];
    }
    if (i < D * D) {
        int k = i >> 7;
        int j = i & 127;
        g_Wcat[i] = (j < DLAT) ? Wmu[k * DLAT + j] : Wls[k * DLAT + (j - DLAT)];
    }
}

// ---------------- degree count over dst ----------------
__global__ void k_count(const int* __restrict__ ei, int E) {
    int e = blockIdx.x * blockDim.x + threadIdx.x;
    if (e < E) atomicAdd(&g_cnt[ei[E + e]], 1);
}

// ---------------- scan phase A: block sums + degree-derived values ----------
__global__ void __launch_bounds__(SCAN_B) k_scanA(int N) {
    __shared__ int ws[8];
    int i = blockIdx.x * SCAN_B + threadIdx.x;
    int v = (i < N) ? g_cnt[i] : 0;
    if (i < N) {
        float d = (float)v + 1.0f;
        g_isd[i] = rsqrtf(d);
        g_invdeg[i] = 1.0f / d;
    }
    int lane = threadIdx.x & 31, wid = threadIdx.x >> 5;
    int r = v;
#pragma unroll
    for (int o = 16; o; o >>= 1) r += __shfl_down_sync(0xffffffffu, r, o);
    if (lane == 0) ws[wid] = r;
    __syncthreads();
    if (threadIdx.x < 8) {
        int t = ws[threadIdx.x];
#pragma unroll
        for (int o = 4; o; o >>= 1) t += __shfl_down_sync(0xffu, t, o);
        if (threadIdx.x == 0) g_bsum[blockIdx.x] = t;
    }
}

// ---------------- scan phase B: exclusive scan of block sums (nb<=256) ------
__global__ void __launch_bounds__(SCAN_B) k_scanB(int nb, int E, int N) {
    __shared__ int ws[8];
    int tid = threadIdx.x;
    int v = (tid < nb) ? g_bsum[tid] : 0;
    int lane = tid & 31, wid = tid >> 5;
    int x = v;
#pragma unroll
    for (int o = 1; o < 32; o <<= 1) {
        int n = __shfl_up_sync(0xffffffffu, x, o);
        if (lane >= o) x += n;
    }
    if (lane == 31) ws[wid] = x;
    __syncthreads();
    if (wid == 0 && lane < 8) {
        int t = ws[lane];
#pragma unroll
        for (int o = 1; o < 8; o <<= 1) {
            int n = __shfl_up_sync(0xffu, t, o);
            if (lane >= o) t += n;
        }
        ws[lane] = t;
    }
    __syncthreads();
    int incl = x + (wid > 0 ? ws[wid - 1] : 0);
    if (tid < nb) g_boff[tid] = incl - v;
    if (tid == 0) g_rowptr[N] = E;
}

// ---------------- scan phase C: local exclusive scan + offset ---------------
__global__ void __launch_bounds__(SCAN_B) k_scanC(int N) {
    __shared__ int ws[8];
    int i = blockIdx.x * SCAN_B + threadIdx.x;
    int v = (i < N) ? g_cnt[i] : 0;
    int lane = threadIdx.x & 31, wid = threadIdx.x >> 5;
    int x = v;
#pragma unroll
    for (int o = 1; o < 32; o <<= 1) {
        int n = __shfl_up_sync(0xffffffffu, x, o);
        if (lane >= o) x += n;
    }
    if (lane == 31) ws[wid] = x;
    __syncthreads();
    if (wid == 0 && lane < 8) {
        int t = ws[lane];
#pragma unroll
        for (int o = 1; o < 8; o <<= 1) {
            int n = __shfl_up_sync(0xffu, t, o);
            if (lane >= o) t += n;
        }
        ws[lane] = t;
    }
    __syncthreads();
    int ex = x - v + (wid > 0 ? ws[wid - 1] : 0) + g_boff[blockIdx.x];
    if (i < N) {
        g_rowptr[i] = ex;
        g_cursor[i] = ex;
    }
}

// ---------------- scatter edges into CSR slots ----------------
__global__ void k_scatter(const int* __restrict__ ei, int E) {
    int e = blockIdx.x * blockDim.x + threadIdx.x;
    if (e < E) {
        int s = ei[e];
        int d = ei[E + e];
        int pos = atomicAdd(&g_cursor[d], 1);
        g_srcs[pos] = s;
        g_w[pos] = g_isd[s] * g_isd[d];
    }
}

// ---------------- GEMM: C[M,128] = A[M,128] @ B[128,128], f32x2 FMA --------
// MODE 0: A=x, B=W1           -> g_h0 = raw
// MODE 1: A=g_aggh, B=g_Wcat  -> out_mu / out_ls = raw + bcat (split)
template <int MODE>
__global__ void __launch_bounds__(128) k_gemm(const float* __restrict__ Aext,
                                              const float* __restrict__ Bext,
                                              int M,
                                              float* __restrict__ out_mu,
                                              float* __restrict__ out_ls) {
    __shared__ float As[16][68];
    __shared__ float Bs[16][128];

    const float* A = (MODE == 0) ? Aext : g_aggh;
    const float* B = (MODE == 0) ? Bext : g_Wcat;

    int tid = threadIdx.x;
    int tx = tid & 15;
    int ty = tid >> 4;
    int row0 = blockIdx.x * 64;

    unsigned long long accp[8][4];   // 8 rows x 4 col-pairs (f32x2)
#pragma unroll
    for (int i = 0; i < 8; i++)
#pragma unroll
        for (int j = 0; j < 4; j++) accp[i][j] = 0ull;

    for (int k0 = 0; k0 < D; k0 += 16) {
#pragma unroll
        for (int li = 0; li < 2; li++) {
            int f = tid * 2 + li;
            int r = f >> 2;
            int kq = (f & 3) * 4;
            float4 v = make_float4(0.f, 0.f, 0.f, 0.f);
            if (row0 + r < M)
                v = *(const float4*)&A[(size_t)(row0 + r) * D + k0 + kq];
            As[kq + 0][r] = v.x;
            As[kq + 1][r] = v.y;
            As[kq + 2][r] = v.z;
            As[kq + 3][r] = v.w;
        }
        const float4* bsrc = (const float4*)(B + (size_t)k0 * D);
#pragma unroll
        for (int j = 0; j < 4; j++)
            ((float4*)Bs)[tid + 128 * j] = bsrc[tid + 128 * j];

        __syncthreads();

#pragma unroll
        for (int k = 0; k < 16; k++) {
            float4 a0 = *(float4*)&As[k][ty * 8];
            float4 a1 = *(float4*)&As[k][ty * 8 + 4];
            float4 b0 = *(float4*)&Bs[k][tx * 8];
            float4 b1 = *(float4*)&Bs[k][tx * 8 + 4];
            unsigned long long bp[4];
            bp[0] = pack2(b0.x, b0.y);
            bp[1] = pack2(b0.z, b0.w);
            bp[2] = pack2(b1.x, b1.y);
            bp[3] = pack2(b1.z, b1.w);
            float a[8] = {a0.x, a0.y, a0.z, a0.w, a1.x, a1.y, a1.z, a1.w};
#pragma unroll
            for (int i = 0; i < 8; i++) {
                unsigned long long ap = pack2(a[i], a[i]);
#pragma unroll
                for (int j = 0; j < 4; j++)
                    accp[i][j] = fma2(ap, bp[j], accp[i][j]);
            }
        }
        __syncthreads();
    }

    int colbase = tx * 8;
#pragma unroll
    for (int i = 0; i < 8; i++) {
        int row = row0 + ty * 8 + i;
        if (row < M) {
            float4 v0, v1;
            unpack2(accp[i][0], v0.x, v0.y);
            unpack2(accp[i][1], v0.z, v0.w);
            unpack2(accp[i][2], v1.x, v1.y);
            unpack2(accp[i][3], v1.z, v1.w);
            if (MODE == 0) {
                *(float4*)&g_h0[(size_t)row * D + colbase]     = v0;
                *(float4*)&g_h0[(size_t)row * D + colbase + 4] = v1;
            } else {
                float4 bi0 = *(const float4*)&g_bcat[colbase];
                float4 bi1 = *(const float4*)&g_bcat[colbase + 4];
                v0.x += bi0.x; v0.y += bi0.y; v0.z += bi0.z; v0.w += bi0.w;
                v1.x += bi1.x; v1.y += bi1.y; v1.z += bi1.z; v1.w += bi1.w;
                if (colbase < DLAT) {
                    *(float4*)&out_mu[(size_t)row * DLAT + colbase]     = v0;
                    *(float4*)&out_mu[(size_t)row * DLAT + colbase + 4] = v1;
                } else {
                    *(float4*)&out_ls[(size_t)row * DLAT + colbase - DLAT]     = v0;
                    *(float4*)&out_ls[(size_t)row * DLAT + colbase - DLAT + 4] = v1;
                }
            }
        }
    }
}

// ---------------- CSR aggregation: warp per node, no output atomics -------
// MODE 0: g_h[i]   = sum_e w*g_h0[src] + invdeg[i]*g_h0[i] + b1  (+ fused BN partials)
// MODE 1: g_aggh[i]= sum_e w*g_h [src] + invdeg[i]*g_h [i]
template <int MODE>
__global__ void __launch_bounds__(256) k_agg(const float* __restrict__ b1, int N) {
    __shared__ float sh_s[D];
    __shared__ float sh_s2[D];
    if (MODE == 0) {
        if (threadIdx.x < D) { sh_s[threadIdx.x] = 0.f; sh_s2[threadIdx.x] = 0.f; }
        __syncthreads();
    }

    int gwarp = (blockIdx.x * blockDim.x + threadIdx.x) >> 5;
    int lane = threadIdx.x & 31;
    const float* feat = (MODE == 0) ? g_h0 : g_h;

    float4 acc = make_float4(0.f, 0.f, 0.f, 0.f);
    bool active = (gwarp < N);
    if (active) {
        int node = gwarp;
        int beg = g_rowptr[node];
        int end = g_rowptr[node + 1];
        float id = g_invdeg[node];

        float4 self = *(const float4*)&feat[(size_t)node * D + lane * 4];
        acc.x = self.x * id; acc.y = self.y * id;
        acc.z = self.z * id; acc.w = self.w * id;
        if (MODE == 0) {
            float4 bi = *(const float4*)&b1[lane * 4];
            acc.x += bi.x; acc.y += bi.y; acc.z += bi.z; acc.w += bi.w;
        }

        for (int base = beg; base < end; base += 32) {
            int t = base + lane;
            int s = 0; float w = 0.f;
            if (t < end) { s = g_srcs[t]; w = g_w[t]; }
            int m = min(32, end - base);
            for (int j = 0; j < m; j++) {
                int sj = __shfl_sync(0xffffffffu, s, j);
                float wj = __shfl_sync(0xffffffffu, w, j);
                const float4 v = *(const float4*)&feat[(size_t)sj * D + lane * 4];
                acc.x = fmaf(wj, v.x, acc.x);
                acc.y = fmaf(wj, v.y, acc.y);
                acc.z = fmaf(wj, v.z, acc.z);
                acc.w = fmaf(wj, v.w, acc.w);
            }
        }

        float* out = (MODE == 0) ? g_h : g_aggh;
        *(float4*)&out[(size_t)gwarp * D + lane * 4] = acc;
    }

    if (MODE == 0) {
        if (active) {
            int c = lane * 4;
            atomicAdd(&sh_s[c + 0], acc.x);  atomicAdd(&sh_s2[c + 0], acc.x * acc.x);
            atomicAdd(&sh_s[c + 1], acc.y);  atomicAdd(&sh_s2[c + 1], acc.y * acc.y);
            atomicAdd(&sh_s[c + 2], acc.z);  atomicAdd(&sh_s2[c + 2], acc.z * acc.z);
            atomicAdd(&sh_s[c + 3], acc.w);  atomicAdd(&sh_s2[c + 3], acc.w * acc.w);
        }
        __syncthreads();
        if (threadIdx.x < D) {
            atomicAdd(&g_sum[threadIdx.x], sh_s[threadIdx.x]);
            atomicAdd(&g_sumsq[threadIdx.x], sh_s2[threadIdx.x]);
        }
    }
}

// ---------------- BN finalize + apply (ReLU) ----------------
__global__ void k_bnfin(const float* __restrict__ gamma, const float* __restrict__ beta, int N) {
    int c = threadIdx.x;
    float invN = 1.0f / (float)N;
    float mean = g_sum[c] * invN;
    float var = fmaxf(g_sumsq[c] * invN - mean * mean, 0.0f);
    float sc = gamma[c] * rsqrtf(var + BN_EPS);
    g_scale[c] = sc;
    g_shift[c] = beta[c] - mean * sc;
}

__global__ void k_bnapply(int N) {
    int i = blockIdx.x * blockDim.x + threadIdx.x;
    int total = N * (D / 4);
    if (i < total) {
        int c4 = i & 31;
        float4 v = ((float4*)g_h)[i];
        float4 sc = ((float4*)g_scale)[c4];
        float4 sh = ((float4*)g_shift)[c4];
        v.x = fmaxf(fmaf(v.x, sc.x, sh.x), 0.0f);
        v.y = fmaxf(fmaf(v.y, sc.y, sh.y), 0.0f);
        v.z = fmaxf(fmaf(v.z, sc.z, sh.z), 0.0f);
        v.w = fmaxf(fmaf(v.w, sc.w, sh.w), 0.0f);
        ((float4*)g_h)[i] = v;
    }
}

// ---------------- launch ----------------
extern "C" void kernel_launch(void* const* d_in, const int* in_sizes, int n_in,
                              void* d_out, int out_size) {
    const float* x     = (const float*)d_in[0];
    const int*   ei    = (const int*)d_in[1];     // int32
    const float* W1    = (const float*)d_in[2];
    const float* b1    = (const float*)d_in[3];
    const float* gamma = (const float*)d_in[4];
    const float* beta  = (const float*)d_in[5];
    const float* Wmu   = (const float*)d_in[6];
    const float* bmu   = (const float*)d_in[7];
    const float* Wls   = (const float*)d_in[8];
    const float* bls   = (const float*)d_in[9];

    int N = in_sizes[0] / D;
    int E = in_sizes[1] / 2;

    float* out_mu = (float*)d_out;
    float* out_ls = (float*)d_out + (size_t)N * DLAT;

    int init_threads = (N > D * D) ? N : D * D;
    int nb = (N + SCAN_B - 1) / SCAN_B;
    int gemm_blocks = (N + 63) / 64;
    int agg_blocks = (N + 7) / 8;

    // --- CSR build; gemm0 placed 4th so the profiler's fixed slot lands on it ---
    k_init<<<(init_threads + 255) / 256, 256>>>(Wmu, Wls, bmu, bls, N);   // 1
    k_count<<<(E + 255) / 256, 256>>>(ei, E);                             // 2
    k_scanA<<<nb, SCAN_B>>>(N);                                           // 3
    k_gemm<0><<<gemm_blocks, 128>>>(x, W1, N, nullptr, nullptr);          // 4 (profiled)
    k_scanB<<<1, SCAN_B>>>(nb, E, N);                                     // 5
    k_scanC<<<nb, SCAN_B>>>(N);                                           // 6
    k_scatter<<<(E + 255) / 256, 256>>>(ei, E);                           // 7

    // --- conv1 aggregation (+fused BN stats) ---
    k_agg<0><<<agg_blocks, 256>>>(b1, N);

    // --- BatchNorm finalize + apply + ReLU ---
    k_bnfin<<<1, 128>>>(gamma, beta, N);
    k_bnapply<<<(N * (D / 4) + 255) / 256, 256>>>(N);

    // --- conv2: aggregate h first (linearity), then fused [Wmu|Wls] GEMM ---
    k_agg<1><<<agg_blocks, 256>>>(nullptr, N);
    k_gemm<1><<<gemm_blocks, 128>>>(nullptr, nullptr, N, out_mu, out_ls);
}

// round 7
// speedup vs baseline: 1.1226x; 1.1226x over previous
#include <cuda_runtime.h>

// ---------------- problem constants ----------------
#define NMAX 50000
#define EMAX 800000
#define D    128
#define DLAT 64
#define BN_EPS 1e-5f
#define SCAN_B 256
#define NBLK ((NMAX + SCAN_B - 1) / SCAN_B)

// ---------------- packed f32x2 helpers (Blackwell double-rate fp32) --------
__device__ __forceinline__ unsigned long long pack2(float lo, float hi) {
    unsigned long long r;
    asm("mov.b64 %0, {%1, %2};" : "=l"(r) : "f"(lo), "f"(hi));
    return r;
}
__device__ __forceinline__ unsigned long long fma2(unsigned long long a,
                                                   unsigned long long b,
                                                   unsigned long long c) {
    unsigned long long d;
    asm("fma.rn.f32x2 %0, %1, %2, %3;" : "=l"(d) : "l"(a), "l"(b), "l"(c));
    return d;
}
__device__ __forceinline__ void unpack2(unsigned long long v, float& lo, float& hi) {
    asm("mov.b64 {%0, %1}, %2;" : "=f"(lo), "=f"(hi) : "l"(v));
}

// ---------------- cp.async helpers ----------------
__device__ __forceinline__ void cp_async16(void* smem_dst, const void* gmem_src) {
    unsigned smem = (unsigned)__cvta_generic_to_shared(smem_dst);
    asm volatile("cp.async.ca.shared.global [%0], [%1], 16;\n"
                 :: "r"(smem), "l"(__cvta_generic_to_global(gmem_src)));
}
__device__ __forceinline__ void cp_commit() {
    asm volatile("cp.async.commit_group;\n");
}
__device__ __forceinline__ void cp_wait0() {
    asm volatile("cp.async.wait_group 0;\n");
}

// ---------------- scratch (device globals; no allocation) ----------------
__device__ int   g_cnt[NMAX];
__device__ int   g_rowptr[NMAX + 1];
__device__ int   g_cursor[NMAX];
__device__ int   g_srcs[EMAX];
__device__ float g_w[EMAX];
__device__ int   g_bsum[NBLK];
__device__ int   g_boff[NBLK];
__device__ float g_isd[NMAX];
__device__ float g_invdeg[NMAX];
__device__ float g_h0[(size_t)NMAX * D];
__device__ float g_h [(size_t)NMAX * D];
__device__ float g_aggh[(size_t)NMAX * D];
__device__ float g_sum[D];
__device__ float g_sumsq[D];
__device__ float g_scale[D];
__device__ float g_shift[D];
__device__ float g_Wcat[D * D];
__device__ float g_bcat[D];

// ---------------- init: zero counters/accums, build Wcat/bcat ----------------
__global__ void k_init(const float* __restrict__ Wmu, const float* __restrict__ Wls,
                       const float* __restrict__ bmu, const float* __restrict__ bls,
                       int N) {
    int i = blockIdx.x * blockDim.x + threadIdx.x;
    if (i < N) g_cnt[i] = 0;
    if (i < D) {
        g_sum[i] = 0.0f;
        g_sumsq[i] = 0.0f;
        g_bcat[i] = (i < DLAT) ? bmu[i] : bls[i - DLAT];
    }
    if (i < D * D) {
        int k = i >> 7;
        int j = i & 127;
        g_Wcat[i] = (j < DLAT) ? Wmu[k * DLAT + j] : Wls[k * DLAT + (j - DLAT)];
    }
}

// ---------------- degree count over dst ----------------
__global__ void k_count(const int* __restrict__ ei, int E) {
    int e = blockIdx.x * blockDim.x + threadIdx.x;
    if (e < E) atomicAdd(&g_cnt[ei[E + e]], 1);
}

// ---------------- scan phase A: block sums + degree-derived values ----------
__global__ void __launch_bounds__(SCAN_B) k_scanA(int N) {
    __shared__ int ws[8];
    int i = blockIdx.x * SCAN_B + threadIdx.x;
    int v = (i < N) ? g_cnt[i] : 0;
    if (i < N) {
        float d = (float)v + 1.0f;
        g_isd[i] = rsqrtf(d);
        g_invdeg[i] = 1.0f / d;
    }
    int lane = threadIdx.x & 31, wid = threadIdx.x >> 5;
    int r = v;
#pragma unroll
    for (int o = 16; o; o >>= 1) r += __shfl_down_sync(0xffffffffu, r, o);
    if (lane == 0) ws[wid] = r;
    __syncthreads();
    if (threadIdx.x < 8) {
        int t = ws[threadIdx.x];
#pragma unroll
        for (int o = 4; o; o >>= 1) t += __shfl_down_sync(0xffu, t, o);
        if (threadIdx.x == 0) g_bsum[blockIdx.x] = t;
    }
}

// ---------------- scan phase B: exclusive scan of block sums (nb<=256) ------
__global__ void __launch_bounds__(SCAN_B) k_scanB(int nb, int E, int N) {
    __shared__ int ws[8];
    int tid = threadIdx.x;
    int v = (tid < nb) ? g_bsum[tid] : 0;
    int lane = tid & 31, wid = tid >> 5;
    int x = v;
#pragma unroll
    for (int o = 1; o < 32; o <<= 1) {
        int n = __shfl_up_sync(0xffffffffu, x, o);
        if (lane >= o) x += n;
    }
    if (lane == 31) ws[wid] = x;
    __syncthreads();
    if (wid == 0 && lane < 8) {
        int t = ws[lane];
#pragma unroll
        for (int o = 1; o < 8; o <<= 1) {
            int n = __shfl_up_sync(0xffu, t, o);
            if (lane >= o) t += n;
        }
        ws[lane] = t;
    }
    __syncthreads();
    int incl = x + (wid > 0 ? ws[wid - 1] : 0);
    if (tid < nb) g_boff[tid] = incl - v;
    if (tid == 0) g_rowptr[N] = E;
}

// ---------------- scan phase C: local exclusive scan + offset ---------------
__global__ void __launch_bounds__(SCAN_B) k_scanC(int N) {
    __shared__ int ws[8];
    int i = blockIdx.x * SCAN_B + threadIdx.x;
    int v = (i < N) ? g_cnt[i] : 0;
    int lane = threadIdx.x & 31, wid = threadIdx.x >> 5;
    int x = v;
#pragma unroll
    for (int o = 1; o < 32; o <<= 1) {
        int n = __shfl_up_sync(0xffffffffu, x, o);
        if (lane >= o) x += n;
    }
    if (lane == 31) ws[wid] = x;
    __syncthreads();
    if (wid == 0 && lane < 8) {
        int t = ws[lane];
#pragma unroll
        for (int o = 1; o < 8; o <<= 1) {
            int n = __shfl_up_sync(0xffu, t, o);
            if (lane >= o) t += n;
        }
        ws[lane] = t;
    }
    __syncthreads();
    int ex = x - v + (wid > 0 ? ws[wid - 1] : 0) + g_boff[blockIdx.x];
    if (i < N) {
        g_rowptr[i] = ex;
        g_cursor[i] = ex;
    }
}

// ---------------- scatter edges into CSR slots ----------------
__global__ void k_scatter(const int* __restrict__ ei, int E) {
    int e = blockIdx.x * blockDim.x + threadIdx.x;
    if (e < E) {
        int s = ei[e];
        int d = ei[E + e];
        int pos = atomicAdd(&g_cursor[d], 1);
        g_srcs[pos] = s;
        g_w[pos] = g_isd[s] * g_isd[d];
    }
}

// ---------------- GEMM: C[M,128] = A[M,128] @ B[128,128] -------------------
// f32x2 FMA + double-buffered smem + cp.async(B) + reg-staged A, 1 sync/iter.
// MODE 0: A=x, B=W1           -> g_h0 = raw
// MODE 1: A=g_aggh, B=g_Wcat  -> out_mu / out_ls = raw + bcat (split)
template <int MODE>
__global__ void __launch_bounds__(128) k_gemm(const float* __restrict__ Aext,
                                              const float* __restrict__ Bext,
                                              int M,
                                              float* __restrict__ out_mu,
                                              float* __restrict__ out_ls) {
    __shared__ float  As[2][16][68];         // transposed A tiles
    __shared__ float4 Bs[2][16 * 32];        // 16 k-rows x 32 float4

    const float* A = (MODE == 0) ? Aext : g_aggh;
    const float* B = (MODE == 0) ? Bext : g_Wcat;

    int tid = threadIdx.x;
    int tx = tid & 15;
    int ty = tid >> 4;
    int row0 = blockIdx.x * 64;

    // A-load geometry (fixed per thread): two fragments
    int f0 = tid * 2, f1 = tid * 2 + 1;
    int r0 = f0 >> 2, kq0 = (f0 & 3) * 4;
    int r1 = f1 >> 2, kq1 = (f1 & 3) * 4;

    unsigned long long accp[8][4];
#pragma unroll
    for (int i = 0; i < 8; i++)
#pragma unroll
        for (int j = 0; j < 4; j++) accp[i][j] = 0ull;

    // ---- prologue: stage 0 ----
    {
#pragma unroll
        for (int j = 0; j < 4; j++)
            cp_async16(&Bs[0][tid + 128 * j], (const float4*)B + tid + 128 * j);
        cp_commit();
        float4 a0 = make_float4(0.f, 0.f, 0.f, 0.f), a1 = a0;
        if (row0 + r0 < M) a0 = *(const float4*)&A[(size_t)(row0 + r0) * D + kq0];
        if (row0 + r1 < M) a1 = *(const float4*)&A[(size_t)(row0 + r1) * D + kq1];
        As[0][kq0 + 0][r0] = a0.x; As[0][kq0 + 1][r0] = a0.y;
        As[0][kq0 + 2][r0] = a0.z; As[0][kq0 + 3][r0] = a0.w;
        As[0][kq1 + 0][r1] = a1.x; As[0][kq1 + 1][r1] = a1.y;
        As[0][kq1 + 2][r1] = a1.z; As[0][kq1 + 3][r1] = a1.w;
        cp_wait0();
        __syncthreads();
    }

    for (int k0 = 0; k0 < D; k0 += 16) {
        int s = (k0 >> 4) & 1;
        int ns = s ^ 1;
        bool pf = (k0 + 16 < D);

        float4 a0, a1;
        if (pf) {
            // prefetch B (async, no regs) and A (regs) for next stage
#pragma unroll
            for (int j = 0; j < 4; j++)
                cp_async16(&Bs[ns][tid + 128 * j],
                           (const float4*)(B + (size_t)(k0 + 16) * D) + tid + 128 * j);
            cp_commit();
            a0 = make_float4(0.f, 0.f, 0.f, 0.f); a1 = a0;
            if (row0 + r0 < M) a0 = *(const float4*)&A[(size_t)(row0 + r0) * D + k0 + 16 + kq0];
            if (row0 + r1 < M) a1 = *(const float4*)&A[(size_t)(row0 + r1) * D + k0 + 16 + kq1];
        }

        // ---- compute on stage s ----
#pragma unroll
        for (int k = 0; k < 16; k++) {
            float4 av0 = *(float4*)&As[s][k][ty * 8];
            float4 av1 = *(float4*)&As[s][k][ty * 8 + 4];
            float4 b0 = Bs[s][k * 32 + tx * 2];
            float4 b1 = Bs[s][k * 32 + tx * 2 + 1];
            unsigned long long bp[4];
            bp[0] = pack2(b0.x, b0.y);
            bp[1] = pack2(b0.z, b0.w);
            bp[2] = pack2(b1.x, b1.y);
            bp[3] = pack2(b1.z, b1.w);
            float a[8] = {av0.x, av0.y, av0.z, av0.w, av1.x, av1.y, av1.z, av1.w};
#pragma unroll
            for (int i = 0; i < 8; i++) {
                unsigned long long ap = pack2(a[i], a[i]);
#pragma unroll
                for (int j = 0; j < 4; j++)
                    accp[i][j] = fma2(ap, bp[j], accp[i][j]);
            }
        }

        if (pf) {
            As[ns][kq0 + 0][r0] = a0.x; As[ns][kq0 + 1][r0] = a0.y;
            As[ns][kq0 + 2][r0] = a0.z; As[ns][kq0 + 3][r0] = a0.w;
            As[ns][kq1 + 0][r1] = a1.x; As[ns][kq1 + 1][r1] = a1.y;
            As[ns][kq1 + 2][r1] = a1.z; As[ns][kq1 + 3][r1] = a1.w;
            cp_wait0();
        }
        __syncthreads();
    }

    int colbase = tx * 8;
#pragma unroll
    for (int i = 0; i < 8; i++) {
        int row = row0 + ty * 8 + i;
        if (row < M) {
            float4 v0, v1;
            unpack2(accp[i][0], v0.x, v0.y);
            unpack2(accp[i][1], v0.z, v0.w);
            unpack2(accp[i][2], v1.x, v1.y);
            unpack2(accp[i][3], v1.z, v1.w);
            if (MODE == 0) {
                *(float4*)&g_h0[(size_t)row * D + colbase]     = v0;
                *(float4*)&g_h0[(size_t)row * D + colbase + 4] = v1;
            } else {
                float4 bi0 = *(const float4*)&g_bcat[colbase];
                float4 bi1 = *(const float4*)&g_bcat[colbase + 4];
                v0.x += bi0.x; v0.y += bi0.y; v0.z += bi0.z; v0.w += bi0.w;
                v1.x += bi1.x; v1.y += bi1.y; v1.z += bi1.z; v1.w += bi1.w;
                if (colbase < DLAT) {
                    *(float4*)&out_mu[(size_t)row * DLAT + colbase]     = v0;
                    *(float4*)&out_mu[(size_t)row * DLAT + colbase + 4] = v1;
                } else {
                    *(float4*)&out_ls[(size_t)row * DLAT + colbase - DLAT]     = v0;
                    *(float4*)&out_ls[(size_t)row * DLAT + colbase - DLAT + 4] = v1;
                }
            }
        }
    }
}

// ---------------- CSR aggregation: warp per node, no output atomics -------
// MODE 0: g_h[i]   = sum_e w*g_h0[src] + invdeg[i]*g_h0[i] + b1  (+ fused BN partials)
// MODE 1: g_aggh[i]= sum_e w*g_h [src] + invdeg[i]*g_h [i]
template <int MODE>
__global__ void __launch_bounds__(256) k_agg(const float* __restrict__ b1, int N) {
    __shared__ float sh_s[D];
    __shared__ float sh_s2[D];
    if (MODE == 0) {
        if (threadIdx.x < D) { sh_s[threadIdx.x] = 0.f; sh_s2[threadIdx.x] = 0.f; }
        __syncthreads();
    }

    int gwarp = (blockIdx.x * blockDim.x + threadIdx.x) >> 5;
    int lane = threadIdx.x & 31;
    const float* feat = (MODE == 0) ? g_h0 : g_h;

    float4 acc = make_float4(0.f, 0.f, 0.f, 0.f);
    bool active = (gwarp < N);
    if (active) {
        int node = gwarp;
        int beg = g_rowptr[node];
        int end = g_rowptr[node + 1];
        float id = g_invdeg[node];

        float4 self = *(const float4*)&feat[(size_t)node * D + lane * 4];
        acc.x = self.x * id; acc.y = self.y * id;
        acc.z = self.z * id; acc.w = self.w * id;
        if (MODE == 0) {
            float4 bi = *(const float4*)&b1[lane * 4];
            acc.x += bi.x; acc.y += bi.y; acc.z += bi.z; acc.w += bi.w;
        }

        for (int base = beg; base < end; base += 32) {
            int t = base + lane;
            int s = 0; float w = 0.f;
            if (t < end) { s = g_srcs[t]; w = g_w[t]; }
            int m = min(32, end - base);
            for (int j = 0; j < m; j++) {
                int sj = __shfl_sync(0xffffffffu, s, j);
                float wj = __shfl_sync(0xffffffffu, w, j);
                const float4 v = *(const float4*)&feat[(size_t)sj * D + lane * 4];
                acc.x = fmaf(wj, v.x, acc.x);
                acc.y = fmaf(wj, v.y, acc.y);
                acc.z = fmaf(wj, v.z, acc.z);
                acc.w = fmaf(wj, v.w, acc.w);
            }
        }

        float* out = (MODE == 0) ? g_h : g_aggh;
        *(float4*)&out[(size_t)gwarp * D + lane * 4] = acc;
    }

    if (MODE == 0) {
        if (active) {
            int c = lane * 4;
            atomicAdd(&sh_s[c + 0], acc.x);  atomicAdd(&sh_s2[c + 0], acc.x * acc.x);
            atomicAdd(&sh_s[c + 1], acc.y);  atomicAdd(&sh_s2[c + 1], acc.y * acc.y);
            atomicAdd(&sh_s[c + 2], acc.z);  atomicAdd(&sh_s2[c + 2], acc.z * acc.z);
            atomicAdd(&sh_s[c + 3], acc.w);  atomicAdd(&sh_s2[c + 3], acc.w * acc.w);
        }
        __syncthreads();
        if (threadIdx.x < D) {
            atomicAdd(&g_sum[threadIdx.x], sh_s[threadIdx.x]);
            atomicAdd(&g_sumsq[threadIdx.x], sh_s2[threadIdx.x]);
        }
    }
}

// ---------------- BN finalize + apply (ReLU) ----------------
__global__ void k_bnfin(const float* __restrict__ gamma, const float* __restrict__ beta, int N) {
    int c = threadIdx.x;
    float invN = 1.0f / (float)N;
    float mean = g_sum[c] * invN;
    float var = fmaxf(g_sumsq[c] * invN - mean * mean, 0.0f);
    float sc = gamma[c] * rsqrtf(var + BN_EPS);
    g_scale[c] = sc;
    g_shift[c] = beta[c] - mean * sc;
}

__global__ void k_bnapply(int N) {
    int i = blockIdx.x * blockDim.x + threadIdx.x;
    int total = N * (D / 4);
    if (i < total) {
        int c4 = i & 31;
        float4 v = ((float4*)g_h)[i];
        float4 sc = ((float4*)g_scale)[c4];
        float4 sh = ((float4*)g_shift)[c4];
        v.x = fmaxf(fmaf(v.x, sc.x, sh.x), 0.0f);
        v.y = fmaxf(fmaf(v.y, sc.y, sh.y), 0.0f);
        v.z = fmaxf(fmaf(v.z, sc.z, sh.z), 0.0f);
        v.w = fmaxf(fmaf(v.w, sc.w, sh.w), 0.0f);
        ((float4*)g_h)[i] = v;
    }
}

// ---------------- launch ----------------
extern "C" void kernel_launch(void* const* d_in, const int* in_sizes, int n_in,
                              void* d_out, int out_size) {
    const float* x     = (const float*)d_in[0];
    const int*   ei    = (const int*)d_in[1];     // int32
    const float* W1    = (const float*)d_in[2];
    const float* b1    = (const float*)d_in[3];
    const float* gamma = (const float*)d_in[4];
    const float* beta  = (const float*)d_in[5];
    const float* Wmu   = (const float*)d_in[6];
    const float* bmu   = (const float*)d_in[7];
    const float* Wls   = (const float*)d_in[8];
    const float* bls   = (const float*)d_in[9];

    int N = in_sizes[0] / D;
    int E = in_sizes[1] / 2;

    float* out_mu = (float*)d_out;
    float* out_ls = (float*)d_out + (size_t)N * DLAT;

    int init_threads = (N > D * D) ? N : D * D;
    int nb = (N + SCAN_B - 1) / SCAN_B;
    int gemm_blocks = (N + 63) / 64;
    int agg_blocks = (N + 7) / 8;

    // --- CSR build; gemm0 stays 4th so the profiler slot lands on it ---
    k_init<<<(init_threads + 255) / 256, 256>>>(Wmu, Wls, bmu, bls, N);   // 1
    k_count<<<(E + 255) / 256, 256>>>(ei, E);                             // 2
    k_scanA<<<nb, SCAN_B>>>(N);                                           // 3
    k_gemm<0><<<gemm_blocks, 128>>>(x, W1, N, nullptr, nullptr);          // 4 (profiled)
    k_scanB<<<1, SCAN_B>>>(nb, E, N);                                     // 5
    k_scanC<<<nb, SCAN_B>>>(N);                                           // 6
    k_scatter<<<(E + 255) / 256, 256>>>(ei, E);                           // 7

    // --- conv1 aggregation (+fused BN stats) ---
    k_agg<0><<<agg_blocks, 256>>>(b1, N);

    // --- BatchNorm finalize + apply + ReLU ---
    k_bnfin<<<1, 128>>>(gamma, beta, N);
    k_bnapply<<<(N * (D / 4) + 255) / 256, 256>>>(N);

    // --- conv2: aggregate h first (linearity), then fused [Wmu|Wls] GEMM ---
    k_agg<1><<<agg_blocks, 256>>>(nullptr, N);
    k_gemm<1><<<gemm_blocks, 128>>>(nullptr, nullptr, N, out_mu, out_ls);
}